// round 11
// baseline (speedup 1.0000x reference)
#include <cuda_runtime.h>
#include <cstdint>

#define NROWS   16384      // B*T = 4*4096
#define N1      1024
#define N2      2048
#define TW1_STACK_FLOATS (10*512*4)     // 20480 floats per stack (81920 B)
#define TW2_FLOATS       (11*1024*4)    // 45056 floats (180224 B)
#define SMEM1_BYTES ((TW1_STACK_FLOATS + 1024) * 4)   // 86016
#define SMEM2_BYTES ((TW2_FLOATS + 1024) * 4)         // 184320

#define K1_THREADS 384
#define K1_WARPS   12
#define K2_THREADS 320
#define K2_WARPS   10
#define TRIPLES    5461    // full 3-row groups; row 16383 is the tail

// GLU intermediates: a+bias and sigmoid(gate+bias), each (NROWS, 2048) fp32 = 128MB
__device__ float g_a[(size_t)NROWS * N2];
__device__ float g_g[(size_t)NROWS * N2];

// In-register butterfly over n = NREG*32 elements, R rows per thread.
// Element e = r*32 + lane. Stages idx<5: partner in lane bits (shfl.xor);
// stages idx>=5: partner in reg index (local). One twiddle load serves R rows.
template<int NREG, int NSTAGE, int R>
__device__ __forceinline__ void bflyR(float (&v)[NREG][R], const float* __restrict__ tws, int lane) {
    constexpr int TSTAGE = NREG * 64;   // floats per stage = (n/2)*4
    #pragma unroll
    for (int idx = 0; idx < 5; idx++) {
        const int s = 1 << idx;
        const float* tstage = tws + idx * TSTAGE;
        const int i = (lane >> idx) & 1;
        #pragma unroll
        for (int r = 0; r < NREG; r++) {
            const int e = r * 32 + lane;
            const int p = ((e >> (idx + 1)) << idx) | (e & (s - 1));
            float2 t = *(const float2*)(tstage + p * 4 + i * 2);   // own row of 2x2
            #pragma unroll
            for (int q = 0; q < R; q++) {
                float pv = __shfl_xor_sync(0xffffffffu, v[r][q], s);
                float lo = i ? pv : v[r][q];
                float hi = i ? v[r][q] : pv;
                v[r][q] = fmaf(t.x, lo, t.y * hi);
            }
        }
    }
    #pragma unroll
    for (int idx = 5; idx < NSTAGE; idx++) {
        const int rs = 1 << (idx - 5);
        const float* tstage = tws + idx * TSTAGE;
        #pragma unroll
        for (int r = 0; r < NREG; r++) {
            if (r & rs) continue;
            const int r2 = r | rs;
            const int e = r * 32 + lane;
            const int p = ((e >> (idx + 1)) << idx) | (e & ((1 << idx) - 1));
            float4 t = *(const float4*)(tstage + p * 4);
            #pragma unroll
            for (int q = 0; q < R; q++) {
                float lo = v[r][q], hi = v[r2][q];
                v[r][q]  = fmaf(t.x, lo, t.y * hi);
                v[r2][q] = fmaf(t.z, lo, t.w * hi);
            }
        }
    }
}

__device__ __forceinline__ float fast_sigmoid(float z) {
    return __fdividef(1.0f, 1.0f + __expf(-z));
}

// Kernel 1: fc1 butterfly, ONE stack per CTA (stack = blockIdx.x & 3).
// Stacks 0,1 -> g_a (a + bias); stacks 2,3 -> g_g (sigmoid(gate + bias)).
// 384 threads (12 warps), 3 rows per thread.
__global__ void __launch_bounds__(K1_THREADS, 1)
glu_k1(const float* __restrict__ x, const float* __restrict__ tw1,
       const float* __restrict__ b1) {
    extern __shared__ float sm[];
    const int stack = blockIdx.x & 3;
    {
        const float4* src = (const float4*)(tw1 + stack * TW1_STACK_FLOATS);
        float4* d = (float4*)sm;
        for (int i = threadIdx.x; i < TW1_STACK_FLOATS / 4; i += K1_THREADS) d[i] = src[i];
        float* sb = sm + TW1_STACK_FLOATS;
        for (int i = threadIdx.x; i < 1024; i += K1_THREADS) sb[i] = b1[stack * 1024 + i];
    }
    __syncthreads();

    const float* sb = sm + TW1_STACK_FLOATS;
    const int lane = threadIdx.x & 31;
    const int warp = threadIdx.x >> 5;
    const int wg = (blockIdx.x >> 2) * K1_WARPS + warp;
    const int ws = (gridDim.x >> 2) * K1_WARPS;
    const bool isGate = (stack >= 2);
    float* dstBase = (isGate ? g_g : g_a) + (size_t)(stack & 1) * 1024;

    for (int tp = wg; tp < TRIPLES; tp += ws) {
        const float* x0 = x + (size_t)(3 * tp) * N1;
        float v[32][3];
        #pragma unroll
        for (int r = 0; r < 32; r++) {
            const int e = r * 32 + lane;
            v[r][0] = x0[e];
            v[r][1] = x0[N1 + e];
            v[r][2] = x0[2 * N1 + e];
        }
        bflyR<32, 10, 3>(v, sm, lane);

        float* o0 = dstBase + (size_t)(3 * tp) * N2;
        if (isGate) {
            #pragma unroll
            for (int r = 0; r < 32; r++) {
                const int e = r * 32 + lane;
                float bb = sb[e];
                o0[e]          = fast_sigmoid(v[r][0] + bb);
                o0[N2 + e]     = fast_sigmoid(v[r][1] + bb);
                o0[2 * N2 + e] = fast_sigmoid(v[r][2] + bb);
            }
        } else {
            #pragma unroll
            for (int r = 0; r < 32; r++) {
                const int e = r * 32 + lane;
                float bb = sb[e];
                o0[e]          = v[r][0] + bb;
                o0[N2 + e]     = v[r][1] + bb;
                o0[2 * N2 + e] = v[r][2] + bb;
            }
        }
    }

    // Tail: row 16383 (one per stack; handled by the stack's first warp)
    if (wg == 0) {
        const int row = NROWS - 1;
        const float* x0 = x + (size_t)row * N1;
        float v[32][1];
        #pragma unroll
        for (int r = 0; r < 32; r++) v[r][0] = x0[r * 32 + lane];
        bflyR<32, 10, 1>(v, sm, lane);
        float* o0 = dstBase + (size_t)row * N2;
        if (isGate) {
            #pragma unroll
            for (int r = 0; r < 32; r++) {
                const int e = r * 32 + lane;
                o0[e] = fast_sigmoid(v[r][0] + sb[e]);
            }
        } else {
            #pragma unroll
            for (int r = 0; r < 32; r++) {
                const int e = r * 32 + lane;
                o0[e] = v[r][0] + sb[e];
            }
        }
    }
}

// Kernel 2: GLU product fused at load (v = a * g), fc2 butterfly (n=2048),
// keep first 1024 + bias. 320 threads (10 warps), 2 rows per thread.
__global__ void __launch_bounds__(K2_THREADS, 1)
glu_k2(const float* __restrict__ tw2, const float* __restrict__ b2,
       float* __restrict__ out) {
    extern __shared__ float sm[];
    {
        const float4* src = (const float4*)tw2;
        float4* d = (float4*)sm;
        for (int i = threadIdx.x; i < TW2_FLOATS / 4; i += K2_THREADS) d[i] = src[i];
        float* sb = sm + TW2_FLOATS;
        for (int i = threadIdx.x; i < 1024; i += K2_THREADS) sb[i] = b2[i];
    }
    __syncthreads();

    const float* sb = sm + TW2_FLOATS;
    const int lane = threadIdx.x & 31;
    const int warp = threadIdx.x >> 5;
    const int wg = blockIdx.x * K2_WARPS + warp;
    const int ws = gridDim.x * K2_WARPS;

    for (int rp = wg; rp < NROWS / 2; rp += ws) {
        const float* pa = g_a + (size_t)(2 * rp) * N2;
        const float* pg = g_g + (size_t)(2 * rp) * N2;
        float v[64][2];
        #pragma unroll
        for (int r = 0; r < 64; r++) {
            const int e = r * 32 + lane;
            v[r][0] = pa[e] * pg[e];
            v[r][1] = pa[N2 + e] * pg[N2 + e];
        }
        bflyR<64, 11, 2>(v, sm, lane);

        float* o0 = out + (size_t)(2 * rp) * 1024;
        #pragma unroll
        for (int r = 0; r < 32; r++) {   // out_size = 1024: first 32 regs only
            const int e = r * 32 + lane;
            float bb = sb[e];
            o0[e]        = v[r][0] + bb;
            o0[1024 + e] = v[r][1] + bb;
        }
    }
}

extern "C" void kernel_launch(void* const* d_in, const int* in_sizes, int n_in,
                              void* d_out, int out_size) {
    const float* x   = (const float*)d_in[0];
    const float* tw1 = (const float*)d_in[1];
    const float* b1  = (const float*)d_in[2];
    const float* tw2 = (const float*)d_in[3];
    const float* b2  = (const float*)d_in[4];
    float* out = (float*)d_out;

    cudaFuncSetAttribute(glu_k1, cudaFuncAttributeMaxDynamicSharedMemorySize, SMEM1_BYTES);
    cudaFuncSetAttribute(glu_k2, cudaFuncAttributeMaxDynamicSharedMemorySize, SMEM2_BYTES);

    glu_k1<<<148, K1_THREADS, SMEM1_BYTES>>>(x, tw1, b1);   // 37 row-groups x 4 stacks
    glu_k2<<<148, K2_THREADS, SMEM2_BYTES>>>(tw2, b2, out);
}

// round 12
// speedup vs baseline: 1.0198x; 1.0198x over previous
#include <cuda_runtime.h>
#include <cstdint>

#define NROWS   16384      // B*T = 4*4096
#define N1      1024
#define N2      2048
#define TW1_STACK_FLOATS (10*512*4)     // 20480 floats per stack (81920 B)
#define TW2_FLOATS       (11*1024*4)    // 45056 floats (180224 B)
#define SMEM1_BYTES ((TW1_STACK_FLOATS + 1024) * 4)   // 86016
#define SMEM2_BYTES ((TW2_FLOATS + 1024) * 4)         // 184320

#define K1_THREADS 384
#define K1_WARPS   12
#define K2_THREADS 320
#define K2_WARPS   10
#define TRIPLES    5461    // full 3-row groups; row 16383 is the tail

// GLU intermediates: a+bias and sigmoid(gate+bias), each (NROWS, 2048) fp32 = 128MB
__device__ float g_a[(size_t)NROWS * N2];
__device__ float g_g[(size_t)NROWS * N2];

// In-register butterfly over n = NREG*32 elements, R rows per thread.
// Element e = r*32 + lane. Stages idx<5: partner in lane bits (shfl.xor);
// stages idx>=5: partner in reg index (local). One twiddle load serves R rows.
template<int NREG, int NSTAGE, int R>
__device__ __forceinline__ void bflyR(float (&v)[NREG][R], const float* __restrict__ tws, int lane) {
    constexpr int TSTAGE = NREG * 64;   // floats per stage = (n/2)*4
    #pragma unroll
    for (int idx = 0; idx < 5; idx++) {
        const int s = 1 << idx;
        const float* tstage = tws + idx * TSTAGE;
        const int i = (lane >> idx) & 1;
        #pragma unroll
        for (int r = 0; r < NREG; r++) {
            const int e = r * 32 + lane;
            const int p = ((e >> (idx + 1)) << idx) | (e & (s - 1));
            float2 t = *(const float2*)(tstage + p * 4 + i * 2);   // own row of 2x2
            #pragma unroll
            for (int q = 0; q < R; q++) {
                float pv = __shfl_xor_sync(0xffffffffu, v[r][q], s);
                float lo = i ? pv : v[r][q];
                float hi = i ? v[r][q] : pv;
                v[r][q] = fmaf(t.x, lo, t.y * hi);
            }
        }
    }
    #pragma unroll
    for (int idx = 5; idx < NSTAGE; idx++) {
        const int rs = 1 << (idx - 5);
        const float* tstage = tws + idx * TSTAGE;
        #pragma unroll
        for (int r = 0; r < NREG; r++) {
            if (r & rs) continue;
            const int r2 = r | rs;
            const int e = r * 32 + lane;
            const int p = ((e >> (idx + 1)) << idx) | (e & ((1 << idx) - 1));
            float4 t = *(const float4*)(tstage + p * 4);
            #pragma unroll
            for (int q = 0; q < R; q++) {
                float lo = v[r][q], hi = v[r2][q];
                v[r][q]  = fmaf(t.x, lo, t.y * hi);
                v[r2][q] = fmaf(t.z, lo, t.w * hi);
            }
        }
    }
}

__device__ __forceinline__ float fast_sigmoid(float z) {
    return __fdividef(1.0f, 1.0f + __expf(-z));
}

// Kernel 1: fc1 butterfly, ONE stack per CTA (stack = blockIdx.x & 3).
// Stacks 0,1 -> g_a (a + bias); stacks 2,3 -> g_g (sigmoid(gate + bias)).
// 384 threads (12 warps), 3 rows per thread.
__global__ void __launch_bounds__(K1_THREADS, 1)
glu_k1(const float* __restrict__ x, const float* __restrict__ tw1,
       const float* __restrict__ b1) {
    extern __shared__ float sm[];
    const int stack = blockIdx.x & 3;
    {
        const float4* src = (const float4*)(tw1 + stack * TW1_STACK_FLOATS);
        float4* d = (float4*)sm;
        for (int i = threadIdx.x; i < TW1_STACK_FLOATS / 4; i += K1_THREADS) d[i] = src[i];
        float* sb = sm + TW1_STACK_FLOATS;
        for (int i = threadIdx.x; i < 1024; i += K1_THREADS) sb[i] = b1[stack * 1024 + i];
    }
    __syncthreads();

    const float* sb = sm + TW1_STACK_FLOATS;
    const int lane = threadIdx.x & 31;
    const int warp = threadIdx.x >> 5;
    const int wg = (blockIdx.x >> 2) * K1_WARPS + warp;
    const int ws = (gridDim.x >> 2) * K1_WARPS;
    const bool isGate = (stack >= 2);
    float* dstBase = (isGate ? g_g : g_a) + (size_t)(stack & 1) * 1024;

    for (int tp = wg; tp < TRIPLES; tp += ws) {
        const float* x0 = x + (size_t)(3 * tp) * N1;
        float v[32][3];
        #pragma unroll
        for (int r = 0; r < 32; r++) {
            const int e = r * 32 + lane;
            v[r][0] = x0[e];
            v[r][1] = x0[N1 + e];
            v[r][2] = x0[2 * N1 + e];
        }
        bflyR<32, 10, 3>(v, sm, lane);

        float* o0 = dstBase + (size_t)(3 * tp) * N2;
        if (isGate) {
            #pragma unroll
            for (int r = 0; r < 32; r++) {
                const int e = r * 32 + lane;
                float bb = sb[e];
                o0[e]          = fast_sigmoid(v[r][0] + bb);
                o0[N2 + e]     = fast_sigmoid(v[r][1] + bb);
                o0[2 * N2 + e] = fast_sigmoid(v[r][2] + bb);
            }
        } else {
            #pragma unroll
            for (int r = 0; r < 32; r++) {
                const int e = r * 32 + lane;
                float bb = sb[e];
                o0[e]          = v[r][0] + bb;
                o0[N2 + e]     = v[r][1] + bb;
                o0[2 * N2 + e] = v[r][2] + bb;
            }
        }
    }

    // Tail: row 16383 (one per stack; handled by the stack's first warp)
    if (wg == 0) {
        const int row = NROWS - 1;
        const float* x0 = x + (size_t)row * N1;
        float v[32][1];
        #pragma unroll
        for (int r = 0; r < 32; r++) v[r][0] = x0[r * 32 + lane];
        bflyR<32, 10, 1>(v, sm, lane);
        float* o0 = dstBase + (size_t)row * N2;
        if (isGate) {
            #pragma unroll
            for (int r = 0; r < 32; r++) {
                const int e = r * 32 + lane;
                o0[e] = fast_sigmoid(v[r][0] + sb[e]);
            }
        } else {
            #pragma unroll
            for (int r = 0; r < 32; r++) {
                const int e = r * 32 + lane;
                o0[e] = v[r][0] + sb[e];
            }
        }
    }
}

// Kernel 2: GLU product fused at load (v = a * g), fc2 butterfly (n=2048),
// keep first 1024 + bias. 320 threads (10 warps), 2 rows per thread.
__global__ void __launch_bounds__(K2_THREADS, 1)
glu_k2(const float* __restrict__ tw2, const float* __restrict__ b2,
       float* __restrict__ out) {
    extern __shared__ float sm[];
    {
        const float4* src = (const float4*)tw2;
        float4* d = (float4*)sm;
        for (int i = threadIdx.x; i < TW2_FLOATS / 4; i += K2_THREADS) d[i] = src[i];
        float* sb = sm + TW2_FLOATS;
        for (int i = threadIdx.x; i < 1024; i += K2_THREADS) sb[i] = b2[i];
    }
    __syncthreads();

    const float* sb = sm + TW2_FLOATS;
    const int lane = threadIdx.x & 31;
    const int warp = threadIdx.x >> 5;
    const int wg = blockIdx.x * K2_WARPS + warp;
    const int ws = gridDim.x * K2_WARPS;

    for (int rp = wg; rp < NROWS / 2; rp += ws) {
        const float* pa = g_a + (size_t)(2 * rp) * N2;
        const float* pg = g_g + (size_t)(2 * rp) * N2;
        float v[64][2];
        #pragma unroll
        for (int r = 0; r < 64; r++) {
            const int e = r * 32 + lane;
            v[r][0] = pa[e] * pg[e];
            v[r][1] = pa[N2 + e] * pg[N2 + e];
        }
        bflyR<64, 11, 2>(v, sm, lane);

        float* o0 = out + (size_t)(2 * rp) * 1024;
        #pragma unroll
        for (int r = 0; r < 32; r++) {   // out_size = 1024: first 32 regs only
            const int e = r * 32 + lane;
            float bb = sb[e];
            o0[e]        = v[r][0] + bb;
            o0[1024 + e] = v[r][1] + bb;
        }
    }
}

extern "C" void kernel_launch(void* const* d_in, const int* in_sizes, int n_in,
                              void* d_out, int out_size) {
    const float* x   = (const float*)d_in[0];
    const float* tw1 = (const float*)d_in[1];
    const float* b1  = (const float*)d_in[2];
    const float* tw2 = (const float*)d_in[3];
    const float* b2  = (const float*)d_in[4];
    float* out = (float*)d_out;

    cudaFuncSetAttribute(glu_k1, cudaFuncAttributeMaxDynamicSharedMemorySize, SMEM1_BYTES);
    cudaFuncSetAttribute(glu_k2, cudaFuncAttributeMaxDynamicSharedMemorySize, SMEM2_BYTES);

    glu_k1<<<148, K1_THREADS, SMEM1_BYTES>>>(x, tw1, b1);   // 37 row-groups x 4 stacks
    glu_k2<<<148, K2_THREADS, SMEM2_BYTES>>>(tw2, b2, out);
}